// round 2
// baseline (speedup 1.0000x reference)
#include <cuda_runtime.h>
#include <math.h>

// Masked scaled-dot-product attention, fp32 flash-style.
// B=16, To=Ti=2048, d=64. Grid (To/64, B), 256 threads.
// Tiles: Q[64x64] (resident), K/V[64x64] streamed, online softmax.

namespace {

constexpr int BM = 64;   // query rows per CTA
constexpr int BN = 64;   // keys per tile
constexpr int DD = 64;   // head dim
constexpr int TO = 2048;
constexpr int TI = 2048;
constexpr float NEG = 1e10f;

__global__ __launch_bounds__(256, 3)
void attn64_kernel(const float* __restrict__ Q,
                   const float* __restrict__ K,
                   const float* __restrict__ V,
                   const int*   __restrict__ M,
                   float*       __restrict__ O)
{
    // Qs: Q tile, layout [d][m] with XOR-swizzled float4 groups along m
    // KPs: K tile [d][n] swizzled; reused as P tile [k][m] swizzled
    // Vs: V tile [k][n] natural row-major
    __shared__ float Qs[DD * BM];
    __shared__ float KPs[DD * BN];
    __shared__ float Vs[BN * DD];

    const int tid = threadIdx.x;
    const int tx = tid & 15;    // key-col group / d-col group
    const int ty = tid >> 4;    // query-row group

    const int b  = blockIdx.y;
    const int q0 = blockIdx.x * BM;

    const float* qb = Q + ((long)b * TO + q0) * DD;
    const float* kb = K + (long)b * TI * DD;
    const float* vb = V + (long)b * TI * DD;
    const int*   mb = M + ((long)b * TO + q0) * (long)TI;

    // ---- load Q tile: transpose to [d][m], swizzle group g' = (m>>2) ^ (d&15)
    {
        const int r  = tid >> 4;          // 0..15
        const int c4 = (tid & 15) << 2;   // 0..60
        #pragma unroll
        for (int it = 0; it < 4; ++it) {
            const int m = r + it * 16;
            const float4 vq = *reinterpret_cast<const float4*>(qb + m * DD + c4);
            const float vv[4] = {vq.x, vq.y, vq.z, vq.w};
            #pragma unroll
            for (int j = 0; j < 4; ++j) {
                const int d = c4 + j;
                const int g = (m >> 2) ^ (d & 15);
                Qs[d * BM + (g << 2) + (m & 3)] = vv[j];
            }
        }
    }

    float acc[4][4];
    float mrow[4], lrow[4];
    #pragma unroll
    for (int i = 0; i < 4; ++i) {
        mrow[i] = -1e30f;
        lrow[i] = 0.0f;
        #pragma unroll
        for (int j = 0; j < 4; ++j) acc[i][j] = 0.0f;
    }

    for (int t0 = 0; t0 < TI; t0 += BN) {
        __syncthreads();  // previous GEMM2 done with KPs(P)/Vs

        // ---- load K tile (transposed + swizzled) and V tile (natural)
        {
            const int r  = tid >> 4;
            const int c4 = (tid & 15) << 2;
            #pragma unroll
            for (int it = 0; it < 4; ++it) {
                const int n = r + it * 16;
                const float4 vk = *reinterpret_cast<const float4*>(kb + (long)(t0 + n) * DD + c4);
                const float vv[4] = {vk.x, vk.y, vk.z, vk.w};
                #pragma unroll
                for (int j = 0; j < 4; ++j) {
                    const int d = c4 + j;
                    const int g = (n >> 2) ^ (d & 15);
                    KPs[d * BN + (g << 2) + (n & 3)] = vv[j];
                }
                const float4 vvv = *reinterpret_cast<const float4*>(vb + (long)(t0 + n) * DD + c4);
                *reinterpret_cast<float4*>(&Vs[n * DD + c4]) = vvv;
            }
        }
        __syncthreads();

        // ---- GEMM1: S = Q K^T (thread tile: rows ty*4.., cols tx*4..)
        float s[4][4];
        #pragma unroll
        for (int i = 0; i < 4; ++i)
            #pragma unroll
            for (int j = 0; j < 4; ++j) s[i][j] = 0.0f;

        #pragma unroll 16
        for (int kk = 0; kk < DD; ++kk) {
            const int swa = ((ty ^ (kk & 15)) << 2);
            const int swb = ((tx ^ (kk & 15)) << 2);
            const float4 a  = *reinterpret_cast<const float4*>(&Qs[kk * BM + swa]);
            const float4 bf = *reinterpret_cast<const float4*>(&KPs[kk * BN + swb]);
            const float av[4] = {a.x, a.y, a.z, a.w};
            const float bv[4] = {bf.x, bf.y, bf.z, bf.w};
            #pragma unroll
            for (int i = 0; i < 4; ++i)
                #pragma unroll
                for (int j = 0; j < 4; ++j)
                    s[i][j] += av[i] * bv[j];
        }

        // ---- mask + scale (scale 1/sqrt(64) = 0.125 applied only where unmasked)
        #pragma unroll
        for (int i = 0; i < 4; ++i) {
            const int qrow = ty * 4 + i;
            const int4 mm = *reinterpret_cast<const int4*>(
                mb + (long)qrow * TI + t0 + (tx << 2));
            s[i][0] = mm.x ? s[i][0] * 0.125f : -NEG;
            s[i][1] = mm.y ? s[i][1] * 0.125f : -NEG;
            s[i][2] = mm.z ? s[i][2] * 0.125f : -NEG;
            s[i][3] = mm.w ? s[i][3] * 0.125f : -NEG;
        }

        // ---- online softmax (row reduce across tx lanes = lane bits 0..3)
        #pragma unroll
        for (int i = 0; i < 4; ++i) {
            float tm = fmaxf(fmaxf(s[i][0], s[i][1]), fmaxf(s[i][2], s[i][3]));
            #pragma unroll
            for (int off = 1; off < 16; off <<= 1)
                tm = fmaxf(tm, __shfl_xor_sync(0xffffffffu, tm, off));
            const float mnew = fmaxf(mrow[i], tm);
            const float sf = __expf(mrow[i] - mnew);
            mrow[i] = mnew;
            float ps = 0.0f;
            #pragma unroll
            for (int j = 0; j < 4; ++j) {
                s[i][j] = __expf(s[i][j] - mnew);
                ps += s[i][j];
            }
            #pragma unroll
            for (int off = 1; off < 16; off <<= 1)
                ps += __shfl_xor_sync(0xffffffffu, ps, off);
            lrow[i] = lrow[i] * sf + ps;
            #pragma unroll
            for (int j = 0; j < 4; ++j) acc[i][j] *= sf;
        }

        __syncthreads();  // all threads done reading KPs(K) before overwrite as P

        // ---- store P transposed to KPs: P[k = tx*4+j][m = ty*4+i], swizzled
        #pragma unroll
        for (int j = 0; j < 4; ++j) {
            const int kr = (tx << 2) + j;
            const int g = ty ^ (kr & 15);
            #pragma unroll
            for (int i = 0; i < 4; ++i)
                KPs[kr * BM + (g << 2) + i] = s[i][j];
        }
        __syncthreads();

        // ---- GEMM2: acc += P @ V  (thread tile: rows ty*4.., d-cols tx*4..)
        #pragma unroll 16
        for (int kk = 0; kk < BN; ++kk) {
            const int swa = ((ty ^ (kk & 15)) << 2);
            const float4 a  = *reinterpret_cast<const float4*>(&KPs[kk * BM + swa]);
            const float4 bf = *reinterpret_cast<const float4*>(&Vs[kk * DD + (tx << 2)]);
            const float av[4] = {a.x, a.y, a.z, a.w};
            const float bv[4] = {bf.x, bf.y, bf.z, bf.w};
            #pragma unroll
            for (int i = 0; i < 4; ++i)
                #pragma unroll
                for (int j = 0; j < 4; ++j)
                    acc[i][j] += av[i] * bv[j];
        }
    }

    // ---- epilogue: normalize and store
    #pragma unroll
    for (int i = 0; i < 4; ++i) {
        const float invl = 1.0f / lrow[i];
        const int m = q0 + ty * 4 + i;
        float4 o;
        o.x = acc[i][0] * invl;
        o.y = acc[i][1] * invl;
        o.z = acc[i][2] * invl;
        o.w = acc[i][3] * invl;
        *reinterpret_cast<float4*>(O + ((long)b * TO + m) * DD + (tx << 2)) = o;
    }
}

}  // namespace

extern "C" void kernel_launch(void* const* d_in, const int* in_sizes, int n_in,
                              void* d_out, int out_size)
{
    const float* q = (const float*)d_in[0];
    const float* k = (const float*)d_in[1];
    const float* v = (const float*)d_in[2];
    const int*   m = (const int*)d_in[3];
    float* out = (float*)d_out;

    dim3 grid(TO / BM, 16);  // (32 query tiles, 16 batches)
    dim3 block(256);
    attn64_kernel<<<grid, block>>>(q, k, v, m, out);
}

// round 5
// speedup vs baseline: 1.2131x; 1.2131x over previous
#include <cuda_runtime.h>
#include <math.h>

// Masked scaled-dot-product attention, fp32 flash-style, 8x4 register tiles.
// B=16, To=Ti=2048, d=64. Grid (To/64, B), 128 threads, 4 CTAs/SM.

namespace {

constexpr int BM = 64;   // query rows per CTA
constexpr int BN = 64;   // keys per tile
constexpr int DD = 64;   // head dim
constexpr int TO = 2048;
constexpr int TI = 2048;
constexpr float NEG = 1e10f;

__global__ __launch_bounds__(128, 4)
void attn84_kernel(const float* __restrict__ Q,
                   const float* __restrict__ K,
                   const float* __restrict__ V,
                   const int*   __restrict__ M,
                   float*       __restrict__ O)
{
    // Qs : Q tile [d][m], float4-group swizzle g' = (m>>2) ^ ((d>>2)&15)
    // KPs: K tile [d][n] same swizzle; reused as P tile [n][m] swizzle (n>>2)
    // Vs : V tile [n][d] natural
    __shared__ float Qs[DD * BM];
    __shared__ float KPs[DD * BN];
    __shared__ float Vs[BN * DD];

    const int tid = threadIdx.x;
    const int tx = tid & 15;    // n-group / d-group (4 cols)
    const int ty = tid >> 4;    // m-group (8 rows), 0..7

    const int b  = blockIdx.y;
    const int q0 = blockIdx.x * BM;

    const float* qb = Q + ((long)b * TO + q0) * DD;
    const float* kb = K + (long)b * TI * DD;
    const float* vb = V + (long)b * TI * DD;
    const int*   mb = M + ((long)b * TO + q0) * (long)TI;

    // ---- load Q tile, transposed to [d][m] with swizzle
    {
        const int r  = tid >> 4;          // 0..7
        const int c4 = (tid & 15) << 2;   // d base, = 4*tx
        #pragma unroll
        for (int it = 0; it < 8; ++it) {
            const int m = r + it * 8;
            const float4 vq = *reinterpret_cast<const float4*>(qb + m * DD + c4);
            const float vv[4] = {vq.x, vq.y, vq.z, vq.w};
            const int g = (m >> 2) ^ tx;   // (d>>2)&15 == tx for all j
            #pragma unroll
            for (int j = 0; j < 4; ++j) {
                const int d = c4 + j;
                Qs[d * BM + (g << 2) + (m & 3)] = vv[j];
            }
        }
    }

    float acc[8][4];
    float mrow[8], lrow[8];
    #pragma unroll
    for (int i = 0; i < 8; ++i) {
        mrow[i] = -1e30f;
        lrow[i] = 0.0f;
        #pragma unroll
        for (int j = 0; j < 4; ++j) acc[i][j] = 0.0f;
    }

    for (int t0 = 0; t0 < TI; t0 += BN) {
        __syncthreads();  // previous GEMM2 done with KPs(P)/Vs

        // ---- load K tile (transposed + swizzled) and V tile (natural)
        {
            const int r  = tid >> 4;
            const int c4 = (tid & 15) << 2;
            #pragma unroll
            for (int it = 0; it < 8; ++it) {
                const int n = r + it * 8;
                const float4 vk = *reinterpret_cast<const float4*>(kb + (long)(t0 + n) * DD + c4);
                const float vv[4] = {vk.x, vk.y, vk.z, vk.w};
                const int g = (n >> 2) ^ tx;
                #pragma unroll
                for (int j = 0; j < 4; ++j) {
                    const int d = c4 + j;
                    KPs[d * BN + (g << 2) + (n & 3)] = vv[j];
                }
                const float4 vvv = *reinterpret_cast<const float4*>(vb + (long)(t0 + n) * DD + c4);
                *reinterpret_cast<float4*>(&Vs[n * DD + c4]) = vvv;
            }
        }
        __syncthreads();

        // ---- GEMM1: S = Q K^T  (thread tile: 8 m-rows x 4 n-cols)
        float s[8][4];
        #pragma unroll
        for (int i = 0; i < 8; ++i)
            #pragma unroll
            for (int j = 0; j < 4; ++j) s[i][j] = 0.0f;

        #pragma unroll 8
        for (int kk = 0; kk < DD; ++kk) {
            const int sw = (kk >> 2) & 15;
            const float4 a0 = *reinterpret_cast<const float4*>(
                &Qs[kk * BM + (((2 * ty) ^ sw) << 2)]);
            const float4 a1 = *reinterpret_cast<const float4*>(
                &Qs[kk * BM + (((2 * ty + 1) ^ sw) << 2)]);
            const float4 bf = *reinterpret_cast<const float4*>(
                &KPs[kk * BN + ((tx ^ sw) << 2)]);
            const float av[8] = {a0.x, a0.y, a0.z, a0.w, a1.x, a1.y, a1.z, a1.w};
            const float bv[4] = {bf.x, bf.y, bf.z, bf.w};
            #pragma unroll
            for (int i = 0; i < 8; ++i)
                #pragma unroll
                for (int j = 0; j < 4; ++j)
                    s[i][j] += av[i] * bv[j];
        }

        // ---- mask + scale + online softmax (reduce over tx lanes: xor 1,2,4,8)
        #pragma unroll
        for (int i = 0; i < 8; ++i) {
            const int qrow = ty * 8 + i;
            const int4 mm = *reinterpret_cast<const int4*>(
                mb + (long)qrow * TI + t0 + (tx << 2));
            s[i][0] = mm.x ? s[i][0] * 0.125f : -NEG;
            s[i][1] = mm.y ? s[i][1] * 0.125f : -NEG;
            s[i][2] = mm.z ? s[i][2] * 0.125f : -NEG;
            s[i][3] = mm.w ? s[i][3] * 0.125f : -NEG;

            float tm = fmaxf(fmaxf(s[i][0], s[i][1]), fmaxf(s[i][2], s[i][3]));
            #pragma unroll
            for (int off = 1; off < 16; off <<= 1)
                tm = fmaxf(tm, __shfl_xor_sync(0xffffffffu, tm, off));
            const float mnew = fmaxf(mrow[i], tm);
            const float sf = __expf(mrow[i] - mnew);
            mrow[i] = mnew;
            float ps = 0.0f;
            #pragma unroll
            for (int j = 0; j < 4; ++j) {
                s[i][j] = __expf(s[i][j] - mnew);
                ps += s[i][j];
            }
            #pragma unroll
            for (int off = 1; off < 16; off <<= 1)
                ps += __shfl_xor_sync(0xffffffffu, ps, off);
            lrow[i] = lrow[i] * sf + ps;
            #pragma unroll
            for (int j = 0; j < 4; ++j) acc[i][j] *= sf;
        }

        __syncthreads();  // done reading KPs(K) before overwrite as P

        // ---- store P transposed [n][m], float4 per m-group (conflict-free)
        #pragma unroll
        for (int j = 0; j < 4; ++j) {
            const int n = (tx << 2) + j;        // n>>2 == tx
            float4 p0, p1;
            p0.x = s[0][j]; p0.y = s[1][j]; p0.z = s[2][j]; p0.w = s[3][j];
            p1.x = s[4][j]; p1.y = s[5][j]; p1.z = s[6][j]; p1.w = s[7][j];
            *reinterpret_cast<float4*>(&KPs[n * BM + (((2 * ty) ^ tx) << 2)]) = p0;
            *reinterpret_cast<float4*>(&KPs[n * BM + (((2 * ty + 1) ^ tx) << 2)]) = p1;
        }
        __syncthreads();

        // ---- GEMM2: acc += P @ V
        #pragma unroll 8
        for (int kk = 0; kk < BN; ++kk) {
            const int sw = (kk >> 2) & 15;
            const float4 a0 = *reinterpret_cast<const float4*>(
                &KPs[kk * BM + (((2 * ty) ^ sw) << 2)]);
            const float4 a1 = *reinterpret_cast<const float4*>(
                &KPs[kk * BM + (((2 * ty + 1) ^ sw) << 2)]);
            const float4 bf = *reinterpret_cast<const float4*>(
                &Vs[kk * DD + (tx << 2)]);
            const float av[8] = {a0.x, a0.y, a0.z, a0.w, a1.x, a1.y, a1.z, a1.w};
            const float bv[4] = {bf.x, bf.y, bf.z, bf.w};
            #pragma unroll
            for (int i = 0; i < 8; ++i)
                #pragma unroll
                for (int j = 0; j < 4; ++j)
                    acc[i][j] += av[i] * bv[j];
        }
    }

    // ---- epilogue: normalize and store
    #pragma unroll
    for (int i = 0; i < 8; ++i) {
        const float invl = 1.0f / lrow[i];
        const int m = q0 + ty * 8 + i;
        float4 o;
        o.x = acc[i][0] * invl;
        o.y = acc[i][1] * invl;
        o.z = acc[i][2] * invl;
        o.w = acc[i][3] * invl;
        *reinterpret_cast<float4*>(O + ((long)b * TO + m) * DD + (tx << 2)) = o;
    }
}

}  // namespace

extern "C" void kernel_launch(void* const* d_in, const int* in_sizes, int n_in,
                              void* d_out, int out_size)
{
    const float* q = (const float*)d_in[0];
    const float* k = (const float*)d_in[1];
    const float* v = (const float*)d_in[2];
    const int*   m = (const int*)d_in[3];
    float* out = (float*)d_out;

    dim3 grid(TO / BM, 16);  // (32 query tiles, 16 batches)
    dim3 block(128);
    attn84_kernel<<<grid, block>>>(q, k, v, m, out);
}

// round 6
// speedup vs baseline: 2.1106x; 1.7398x over previous
#include <cuda_runtime.h>
#include <math.h>

// Masked SDPA, tf32 tensor-core flash attention (mma.sync.m16n8k8).
// B=16, To=Ti=2048, d=64. CTA: 128 thr (4 warps), BM=64 rows, BN=64 keys/tile.

namespace {

constexpr int TO = 2048;
constexpr int TI = 2048;
constexpr int DD = 64;
constexpr int BM = 64;
constexpr int BN = 64;
constexpr int ST = 72;            // smem row stride (floats): banks 8j+r pattern
constexpr float NEG = 1e10f;

__device__ __forceinline__ unsigned f2tf32(float f) {
    unsigned u;
    asm("cvt.rna.tf32.f32 %0, %1;" : "=r"(u) : "f"(f));
    return u;
}

__device__ __forceinline__ void mma8(float c[4],
                                     unsigned a0, unsigned a1, unsigned a2, unsigned a3,
                                     unsigned b0, unsigned b1) {
    asm("mma.sync.aligned.m16n8k8.row.col.f32.tf32.tf32.f32 "
        "{%0,%1,%2,%3},{%4,%5,%6,%7},{%8,%9},{%0,%1,%2,%3};"
        : "+f"(c[0]), "+f"(c[1]), "+f"(c[2]), "+f"(c[3])
        : "r"(a0), "r"(a1), "r"(a2), "r"(a3), "r"(b0), "r"(b1));
}

__global__ __launch_bounds__(128, 3)
void attn_tc_kernel(const float* __restrict__ Q,
                    const float* __restrict__ K,
                    const float* __restrict__ V,
                    const int*   __restrict__ M,
                    float*       __restrict__ O)
{
    __shared__ float Ks[BN * ST];   // K tile, natural [token][d] (tf32 bits)
    __shared__ float Vs[BN * ST];   // V tile, natural [token][d] (tf32 bits)

    unsigned* Ku = reinterpret_cast<unsigned*>(Ks);
    unsigned* Vu = reinterpret_cast<unsigned*>(Vs);

    const int tid  = threadIdx.x;
    const int lane = tid & 31;
    const int warp = tid >> 5;
    const int r0 = lane >> 2;      // fragment row group 0..7
    const int jj = lane & 3;       // fragment col-in-group 0..3

    const int b  = blockIdx.y;
    const int q0 = blockIdx.x * BM;
    const int m0 = warp * 16;      // this warp's first query row (in tile)

    const float* qb = Q + ((long)b * TO + q0) * DD;
    const float* kb = K + (long)b * TI * DD;
    const float* vb = V + (long)b * TI * DD;
    const int*   mbA = M + ((long)((long)b * TO + q0 + m0 + r0)) * TI;
    const int*   mbB = mbA + 8L * TI;

    const int srow = tid >> 4;            // 0..7 (staging row)
    const int sc4  = (tid & 15) << 2;     // 0..60 (staging col base)

    // ---- stage Q (tf32) into Ks, then load A-fragments into registers
    #pragma unroll
    for (int i = 0; i < 8; ++i) {
        const int m = srow + i * 8;
        const float4 v4 = *reinterpret_cast<const float4*>(qb + m * DD + sc4);
        unsigned* dst = Ku + m * ST + sc4;
        dst[0] = f2tf32(v4.x); dst[1] = f2tf32(v4.y);
        dst[2] = f2tf32(v4.z); dst[3] = f2tf32(v4.w);
    }
    __syncthreads();

    unsigned qf[8][4];
    #pragma unroll
    for (int kt = 0; kt < 8; ++kt) {
        qf[kt][0] = Ku[(m0 + r0) * ST + 8 * kt + jj];
        qf[kt][1] = Ku[(m0 + r0 + 8) * ST + 8 * kt + jj];
        qf[kt][2] = Ku[(m0 + r0) * ST + 8 * kt + jj + 4];
        qf[kt][3] = Ku[(m0 + r0 + 8) * ST + 8 * kt + jj + 4];
    }
    __syncthreads();

    float acc[8][4];
    #pragma unroll
    for (int dt = 0; dt < 8; ++dt)
        #pragma unroll
        for (int r = 0; r < 4; ++r) acc[dt][r] = 0.0f;

    float mA = -1e30f, mB = -1e30f, lA = 0.0f, lB = 0.0f;

    const unsigned srcA = (lane & ~3) | (jj >> 1);
    const unsigned srcB = srcA | 2;
    const bool odd = (jj & 1) != 0;

    for (int t0 = 0; t0 < TI; t0 += BN) {
        // ---- stage K, V tiles (tf32) — natural layout, stride 72
        #pragma unroll
        for (int i = 0; i < 8; ++i) {
            const int tok = srow + i * 8;
            const float4 kk = *reinterpret_cast<const float4*>(kb + (long)(t0 + tok) * DD + sc4);
            const float4 vv = *reinterpret_cast<const float4*>(vb + (long)(t0 + tok) * DD + sc4);
            unsigned* kd = Ku + tok * ST + sc4;
            unsigned* vd = Vu + tok * ST + sc4;
            kd[0] = f2tf32(kk.x); kd[1] = f2tf32(kk.y);
            kd[2] = f2tf32(kk.z); kd[3] = f2tf32(kk.w);
            vd[0] = f2tf32(vv.x); vd[1] = f2tf32(vv.y);
            vd[2] = f2tf32(vv.z); vd[3] = f2tf32(vv.w);
        }
        __syncthreads();

        // ---- GEMM1: S = Q K^T  (per warp: 16 x 64)
        float s[8][4];
        #pragma unroll
        for (int nt = 0; nt < 8; ++nt)
            #pragma unroll
            for (int r = 0; r < 4; ++r) s[nt][r] = 0.0f;

        #pragma unroll
        for (int kt = 0; kt < 8; ++kt) {
            #pragma unroll
            for (int nt = 0; nt < 8; ++nt) {
                const unsigned b0 = Ku[(8 * nt + r0) * ST + 8 * kt + jj];
                const unsigned b1 = Ku[(8 * nt + r0) * ST + 8 * kt + jj + 4];
                mma8(s[nt], qf[kt][0], qf[kt][1], qf[kt][2], qf[kt][3], b0, b1);
            }
        }

        // ---- mask + scale
        #pragma unroll
        for (int nt = 0; nt < 8; ++nt) {
            const int col = t0 + 8 * nt + 2 * jj;
            const int2 ma = *reinterpret_cast<const int2*>(mbA + col);
            const int2 mb2 = *reinterpret_cast<const int2*>(mbB + col);
            s[nt][0] = ma.x  ? s[nt][0] * 0.125f : -NEG;
            s[nt][1] = ma.y  ? s[nt][1] * 0.125f : -NEG;
            s[nt][2] = mb2.x ? s[nt][2] * 0.125f : -NEG;
            s[nt][3] = mb2.y ? s[nt][3] * 0.125f : -NEG;
        }

        // ---- online softmax (rows rA = r0, rB = r0+8; reduce over lane&3)
        float tmA = -1e30f, tmB = -1e30f;
        #pragma unroll
        for (int nt = 0; nt < 8; ++nt) {
            tmA = fmaxf(tmA, fmaxf(s[nt][0], s[nt][1]));
            tmB = fmaxf(tmB, fmaxf(s[nt][2], s[nt][3]));
        }
        tmA = fmaxf(tmA, __shfl_xor_sync(0xffffffffu, tmA, 1));
        tmA = fmaxf(tmA, __shfl_xor_sync(0xffffffffu, tmA, 2));
        tmB = fmaxf(tmB, __shfl_xor_sync(0xffffffffu, tmB, 1));
        tmB = fmaxf(tmB, __shfl_xor_sync(0xffffffffu, tmB, 2));

        const float mnA = fmaxf(mA, tmA);
        const float mnB = fmaxf(mB, tmB);
        const float sfA = __expf(mA - mnA);
        const float sfB = __expf(mB - mnB);
        mA = mnA; mB = mnB;

        float psA = 0.0f, psB = 0.0f;
        #pragma unroll
        for (int nt = 0; nt < 8; ++nt) {
            s[nt][0] = __expf(s[nt][0] - mnA);
            s[nt][1] = __expf(s[nt][1] - mnA);
            s[nt][2] = __expf(s[nt][2] - mnB);
            s[nt][3] = __expf(s[nt][3] - mnB);
            psA += s[nt][0] + s[nt][1];
            psB += s[nt][2] + s[nt][3];
        }
        psA += __shfl_xor_sync(0xffffffffu, psA, 1);
        psA += __shfl_xor_sync(0xffffffffu, psA, 2);
        psB += __shfl_xor_sync(0xffffffffu, psB, 1);
        psB += __shfl_xor_sync(0xffffffffu, psB, 2);
        lA = lA * sfA + psA;
        lB = lB * sfB + psB;

        #pragma unroll
        for (int dt = 0; dt < 8; ++dt) {
            acc[dt][0] *= sfA; acc[dt][1] *= sfA;
            acc[dt][2] *= sfB; acc[dt][3] *= sfB;
        }

        // ---- GEMM2: acc += P V   (permute P C-frag -> A-frag via shfl)
        #pragma unroll
        for (int kt = 0; kt < 8; ++kt) {
            const float x0 = __shfl_sync(0xffffffffu, s[kt][0], srcA);
            const float x1 = __shfl_sync(0xffffffffu, s[kt][1], srcA);
            const float y0 = __shfl_sync(0xffffffffu, s[kt][2], srcA);
            const float y1 = __shfl_sync(0xffffffffu, s[kt][3], srcA);
            const float z0 = __shfl_sync(0xffffffffu, s[kt][0], srcB);
            const float z1 = __shfl_sync(0xffffffffu, s[kt][1], srcB);
            const float w0 = __shfl_sync(0xffffffffu, s[kt][2], srcB);
            const float w1 = __shfl_sync(0xffffffffu, s[kt][3], srcB);
            const unsigned a0 = f2tf32(odd ? x1 : x0);
            const unsigned a1 = f2tf32(odd ? y1 : y0);
            const unsigned a2 = f2tf32(odd ? z1 : z0);
            const unsigned a3 = f2tf32(odd ? w1 : w0);
            #pragma unroll
            for (int dt = 0; dt < 8; ++dt) {
                const unsigned b0 = Vu[(8 * kt + jj) * ST + 8 * dt + r0];
                const unsigned b1 = Vu[(8 * kt + jj + 4) * ST + 8 * dt + r0];
                mma8(acc[dt], a0, a1, a2, a3, b0, b1);
            }
        }
        __syncthreads();   // done with Ks/Vs before next stage
    }

    // ---- epilogue: normalize, store (rows q0+m0+r0 and +8)
    const float invA = 1.0f / lA;
    const float invB = 1.0f / lB;
    float* oA = O + ((long)b * TO + q0 + m0 + r0) * DD;
    float* oB = oA + 8L * DD;
    #pragma unroll
    for (int dt = 0; dt < 8; ++dt) {
        const int c = 8 * dt + 2 * jj;
        float2 ra, rb;
        ra.x = acc[dt][0] * invA; ra.y = acc[dt][1] * invA;
        rb.x = acc[dt][2] * invB; rb.y = acc[dt][3] * invB;
        *reinterpret_cast<float2*>(oA + c) = ra;
        *reinterpret_cast<float2*>(oB + c) = rb;
    }
}

}  // namespace

extern "C" void kernel_launch(void* const* d_in, const int* in_sizes, int n_in,
                              void* d_out, int out_size)
{
    const float* q = (const float*)d_in[0];
    const float* k = (const float*)d_in[1];
    const float* v = (const float*)d_in[2];
    const int*   m = (const int*)d_in[3];
    float* out = (float*)d_out;

    dim3 grid(TO / BM, 16);
    dim3 block(128);
    attn_tc_kernel<<<grid, block>>>(q, k, v, m, out);
}

// round 7
// speedup vs baseline: 2.8509x; 1.3508x over previous
#include <cuda_runtime.h>
#include <math.h>

// Masked SDPA, tf32 mma.sync flash attention + cp.async double-buffered K/V
// pipeline + ldmatrix K-fragment loads. B=16, To=Ti=2048, d=64.
// CTA: 128 thr (4 warps), BM=64 rows, BN=64 keys/tile, dynamic smem 70KB.

namespace {

constexpr int TO = 2048;
constexpr int TI = 2048;
constexpr int DD = 64;
constexpr int BM = 64;
constexpr int BN = 64;
constexpr int KST = 68;          // K smem row stride (floats): LDSM conflict-free
constexpr int VST = 72;          // V smem row stride (floats): scalar-LDS conflict-free
constexpr int KTILE = BN * KST;  // 4352 floats
constexpr int VTILE = BN * VST;  // 4608 floats
constexpr int SMEM_FLOATS = 2 * KTILE + 2 * VTILE;   // 17920 floats = 71680 B
constexpr float NEG = 1e10f;

__device__ __forceinline__ unsigned f2tf32(float f) {
    unsigned u;
    asm("cvt.rna.tf32.f32 %0, %1;" : "=r"(u) : "f"(f));
    return u;
}

__device__ __forceinline__ void mma8(float c[4],
                                     unsigned a0, unsigned a1, unsigned a2, unsigned a3,
                                     unsigned b0, unsigned b1) {
    asm("mma.sync.aligned.m16n8k8.row.col.f32.tf32.tf32.f32 "
        "{%0,%1,%2,%3},{%4,%5,%6,%7},{%8,%9},{%0,%1,%2,%3};"
        : "+f"(c[0]), "+f"(c[1]), "+f"(c[2]), "+f"(c[3])
        : "r"(a0), "r"(a1), "r"(a2), "r"(a3), "r"(b0), "r"(b1));
}

__device__ __forceinline__ void ldsm4(unsigned& a, unsigned& b, unsigned& c, unsigned& d,
                                      unsigned addr) {
    asm volatile("ldmatrix.sync.aligned.m8n8.x4.shared.b16 {%0,%1,%2,%3}, [%4];"
                 : "=r"(a), "=r"(b), "=r"(c), "=r"(d) : "r"(addr));
}

__device__ __forceinline__ void cp16(float* dst_smem, const float* src) {
    unsigned d = (unsigned)__cvta_generic_to_shared(dst_smem);
    asm volatile("cp.async.cg.shared.global [%0], [%1], 16;" :: "r"(d), "l"(src));
}

__global__ __launch_bounds__(128, 3)
void attn_tc2_kernel(const float* __restrict__ Q,
                     const float* __restrict__ K,
                     const float* __restrict__ V,
                     const int*   __restrict__ M,
                     float*       __restrict__ O)
{
    extern __shared__ float smem[];
    float* Kb0 = smem;
    float* Kb1 = smem + KTILE;
    float* Vb0 = smem + 2 * KTILE;
    float* Vb1 = smem + 2 * KTILE + VTILE;

    const int tid  = threadIdx.x;
    const int lane = tid & 31;
    const int warp = tid >> 5;
    const int r0 = lane >> 2;
    const int jj = lane & 3;

    const int b  = blockIdx.y;
    const int q0 = blockIdx.x * BM;
    const int m0 = warp * 16;

    const float* qb = Q + ((long)b * TO + q0) * DD;
    const float* kb = K + (long)b * TI * DD;
    const float* vb = V + (long)b * TI * DD;
    const int*   mbA = M + ((long)((long)b * TO + q0 + m0 + r0)) * TI;
    const int*   mbB = mbA + 8L * TI;

    const int srow = tid >> 4;            // 0..7
    const int sc4  = (tid & 15) << 2;     // 0..60

    // per-lane LDSM byte offset within K tile:
    //   rows: lanes 0-15 -> tok +(lane&7); lanes 16-31 -> tok +8+(lane&7)
    //   cols: lanes 8-15,24-31 -> +4 floats (k upper half)
    const unsigned koff = (((lane & 7) + ((lane >> 4) << 3)) * KST +
                           (((lane >> 3) & 1) << 2)) * 4u;
    const unsigned kbu0 = (unsigned)__cvta_generic_to_shared(Kb0);
    const unsigned kbu1 = (unsigned)__cvta_generic_to_shared(Kb1);

    // ---- stage Q (tf32 bits) into Vb1, extract A-fragments
    {
        unsigned* qs = reinterpret_cast<unsigned*>(Vb1);
        #pragma unroll
        for (int i = 0; i < 8; ++i) {
            const int m = srow + i * 8;
            const float4 v4 = *reinterpret_cast<const float4*>(qb + m * DD + sc4);
            unsigned* dst = qs + m * VST + sc4;
            dst[0] = f2tf32(v4.x); dst[1] = f2tf32(v4.y);
            dst[2] = f2tf32(v4.z); dst[3] = f2tf32(v4.w);
        }
    }

    // ---- prefetch tile 0 into buffer 0 (overlaps Q extraction)
    #pragma unroll
    for (int i = 0; i < 8; ++i) {
        const int tok = srow + i * 8;
        cp16(Kb0 + tok * KST + sc4, kb + (long)tok * DD + sc4);
        cp16(Vb0 + tok * VST + sc4, vb + (long)tok * DD + sc4);
    }
    asm volatile("cp.async.commit_group;");

    __syncthreads();   // Q visible

    unsigned qf[8][4];
    {
        const unsigned* qs = reinterpret_cast<const unsigned*>(Vb1);
        #pragma unroll
        for (int kt = 0; kt < 8; ++kt) {
            qf[kt][0] = qs[(m0 + r0) * VST + 8 * kt + jj];
            qf[kt][1] = qs[(m0 + r0 + 8) * VST + 8 * kt + jj];
            qf[kt][2] = qs[(m0 + r0) * VST + 8 * kt + jj + 4];
            qf[kt][3] = qs[(m0 + r0 + 8) * VST + 8 * kt + jj + 4];
        }
    }
    __syncthreads();   // Vb1 free for tile-1 prefetch

    // ---- prefetch tile 1 into buffer 1
    #pragma unroll
    for (int i = 0; i < 8; ++i) {
        const int tok = srow + i * 8;
        cp16(Kb1 + tok * KST + sc4, kb + (long)(BN + tok) * DD + sc4);
        cp16(Vb1 + tok * VST + sc4, vb + (long)(BN + tok) * DD + sc4);
    }
    asm volatile("cp.async.commit_group;");

    float acc[8][4];
    #pragma unroll
    for (int dt = 0; dt < 8; ++dt)
        #pragma unroll
        for (int r = 0; r < 4; ++r) acc[dt][r] = 0.0f;

    float mA = -1e30f, mB = -1e30f, lA = 0.0f, lB = 0.0f;

    const unsigned srcA = (lane & ~3) | (jj >> 1);
    const unsigned srcB = srcA | 2;
    const bool odd = (jj & 1) != 0;

    for (int t = 0; t < TI / BN; ++t) {
        asm volatile("cp.async.wait_group 1;");
        __syncthreads();   // tile t resident in buffer t&1

        const unsigned kbu = (t & 1) ? kbu1 : kbu0;
        const float* Vcur = (t & 1) ? Vb1 : Vb0;

        // ---- GEMM1: S = Q K^T via LDSM.x4 (2 n-tiles per load)
        float s[8][4];
        #pragma unroll
        for (int nt = 0; nt < 8; ++nt)
            #pragma unroll
            for (int r = 0; r < 4; ++r) s[nt][r] = 0.0f;

        #pragma unroll
        for (int kt = 0; kt < 8; ++kt) {
            #pragma unroll
            for (int p = 0; p < 4; ++p) {
                unsigned w0, w1, w2, w3;
                ldsm4(w0, w1, w2, w3,
                      kbu + (unsigned)((p * 16 * KST + kt * 8) * 4) + koff);
                const unsigned c0 = f2tf32(__uint_as_float(w0));
                const unsigned c1 = f2tf32(__uint_as_float(w1));
                const unsigned c2 = f2tf32(__uint_as_float(w2));
                const unsigned c3 = f2tf32(__uint_as_float(w3));
                mma8(s[2 * p],     qf[kt][0], qf[kt][1], qf[kt][2], qf[kt][3], c0, c1);
                mma8(s[2 * p + 1], qf[kt][0], qf[kt][1], qf[kt][2], qf[kt][3], c2, c3);
            }
        }

        // ---- mask + scale
        const int tbase = t * BN;
        #pragma unroll
        for (int nt = 0; nt < 8; ++nt) {
            const int col = tbase + 8 * nt + 2 * jj;
            const int2 ma  = *reinterpret_cast<const int2*>(mbA + col);
            const int2 mb2 = *reinterpret_cast<const int2*>(mbB + col);
            s[nt][0] = ma.x  ? s[nt][0] * 0.125f : -NEG;
            s[nt][1] = ma.y  ? s[nt][1] * 0.125f : -NEG;
            s[nt][2] = mb2.x ? s[nt][2] * 0.125f : -NEG;
            s[nt][3] = mb2.y ? s[nt][3] * 0.125f : -NEG;
        }

        // ---- online softmax
        float tmA = -1e30f, tmB = -1e30f;
        #pragma unroll
        for (int nt = 0; nt < 8; ++nt) {
            tmA = fmaxf(tmA, fmaxf(s[nt][0], s[nt][1]));
            tmB = fmaxf(tmB, fmaxf(s[nt][2], s[nt][3]));
        }
        tmA = fmaxf(tmA, __shfl_xor_sync(0xffffffffu, tmA, 1));
        tmA = fmaxf(tmA, __shfl_xor_sync(0xffffffffu, tmA, 2));
        tmB = fmaxf(tmB, __shfl_xor_sync(0xffffffffu, tmB, 1));
        tmB = fmaxf(tmB, __shfl_xor_sync(0xffffffffu, tmB, 2));

        const float mnA = fmaxf(mA, tmA);
        const float mnB = fmaxf(mB, tmB);
        const float sfA = __expf(mA - mnA);
        const float sfB = __expf(mB - mnB);
        mA = mnA; mB = mnB;

        float psA = 0.0f, psB = 0.0f;
        #pragma unroll
        for (int nt = 0; nt < 8; ++nt) {
            s[nt][0] = __expf(s[nt][0] - mnA);
            s[nt][1] = __expf(s[nt][1] - mnA);
            s[nt][2] = __expf(s[nt][2] - mnB);
            s[nt][3] = __expf(s[nt][3] - mnB);
            psA += s[nt][0] + s[nt][1];
            psB += s[nt][2] + s[nt][3];
        }
        psA += __shfl_xor_sync(0xffffffffu, psA, 1);
        psA += __shfl_xor_sync(0xffffffffu, psA, 2);
        psB += __shfl_xor_sync(0xffffffffu, psB, 1);
        psB += __shfl_xor_sync(0xffffffffu, psB, 2);
        lA = lA * sfA + psA;
        lB = lB * sfB + psB;

        #pragma unroll
        for (int dt = 0; dt < 8; ++dt) {
            acc[dt][0] *= sfA; acc[dt][1] *= sfA;
            acc[dt][2] *= sfB; acc[dt][3] *= sfB;
        }

        // ---- GEMM2: acc += P V  (P C-frag -> A-frag via shfl; V raw fp32 + cvt)
        #pragma unroll
        for (int kt = 0; kt < 8; ++kt) {
            const float x0 = __shfl_sync(0xffffffffu, s[kt][0], srcA);
            const float x1 = __shfl_sync(0xffffffffu, s[kt][1], srcA);
            const float y0 = __shfl_sync(0xffffffffu, s[kt][2], srcA);
            const float y1 = __shfl_sync(0xffffffffu, s[kt][3], srcA);
            const float z0 = __shfl_sync(0xffffffffu, s[kt][0], srcB);
            const float z1 = __shfl_sync(0xffffffffu, s[kt][1], srcB);
            const float w0 = __shfl_sync(0xffffffffu, s[kt][2], srcB);
            const float w1 = __shfl_sync(0xffffffffu, s[kt][3], srcB);
            const unsigned a0 = f2tf32(odd ? x1 : x0);
            const unsigned a1 = f2tf32(odd ? y1 : y0);
            const unsigned a2 = f2tf32(odd ? z1 : z0);
            const unsigned a3 = f2tf32(odd ? w1 : w0);
            const float* vr0 = Vcur + (8 * kt + jj) * VST;
            const float* vr1 = Vcur + (8 * kt + jj + 4) * VST;
            #pragma unroll
            for (int dt = 0; dt < 8; ++dt) {
                const unsigned b0 = f2tf32(vr0[8 * dt + r0]);
                const unsigned b1 = f2tf32(vr1[8 * dt + r0]);
                mma8(acc[dt], a0, a1, a2, a3, b0, b1);
            }
        }

        __syncthreads();   // all warps done with buffer t&1

        // ---- prefetch tile t+2 into buffer t&1
        if (t + 2 < TI / BN) {
            float* Kn = (t & 1) ? Kb1 : Kb0;
            float* Vn = (t & 1) ? Vb1 : Vb0;
            const long off = (long)(t + 2) * BN;
            #pragma unroll
            for (int i = 0; i < 8; ++i) {
                const int tok = srow + i * 8;
                cp16(Kn + tok * KST + sc4, kb + (off + tok) * DD + sc4);
                cp16(Vn + tok * VST + sc4, vb + (off + tok) * DD + sc4);
            }
        }
        asm volatile("cp.async.commit_group;");
    }

    // ---- epilogue: normalize, store
    const float invA = 1.0f / lA;
    const float invB = 1.0f / lB;
    float* oA = O + ((long)b * TO + q0 + m0 + r0) * DD;
    float* oB = oA + 8L * DD;
    #pragma unroll
    for (int dt = 0; dt < 8; ++dt) {
        const int c = 8 * dt + 2 * jj;
        float2 ra, rb;
        ra.x = acc[dt][0] * invA; ra.y = acc[dt][1] * invA;
        rb.x = acc[dt][2] * invB; rb.y = acc[dt][3] * invB;
        *reinterpret_cast<float2*>(oA + c) = ra;
        *reinterpret_cast<float2*>(oB + c) = rb;
    }
}

}  // namespace

extern "C" void kernel_launch(void* const* d_in, const int* in_sizes, int n_in,
                              void* d_out, int out_size)
{
    const float* q = (const float*)d_in[0];
    const float* k = (const float*)d_in[1];
    const float* v = (const float*)d_in[2];
    const int*   m = (const int*)d_in[3];
    float* out = (float*)d_out;

    static bool attr_set = false;
    if (!attr_set) {
        cudaFuncSetAttribute(attn_tc2_kernel,
                             cudaFuncAttributeMaxDynamicSharedMemorySize,
                             SMEM_FLOATS * (int)sizeof(float));
        attr_set = true;
    }

    dim3 grid(TO / BM, 16);
    dim3 block(128);
    attn_tc2_kernel<<<grid, block, SMEM_FLOATS * sizeof(float)>>>(q, k, v, m, out);
}

// round 8
// speedup vs baseline: 5.4713x; 1.9191x over previous
#include <cuda_runtime.h>
#include <cuda_fp16.h>
#include <math.h>

// Masked SDPA, fp16 mma.sync.m16n8k16 flash attention.
// Pre-pass converts Q/K/V fp32 -> fp16 into device-global buffers.
// Main: cp.async double-buffered K/V halves, ldmatrix fragments, fp32 softmax.
// B=16, To=Ti=2048, d=64. CTA: 128 thr (4 warps), 64x64 tiles.

namespace {

constexpr int TO = 2048;
constexpr int TI = 2048;
constexpr int DD = 64;
constexpr int BM = 64;
constexpr int BN = 64;
constexpr int NEL = 16 * 2048 * 64;     // elements per tensor
constexpr int STH = 72;                 // smem row stride in halves (144B)
constexpr int TILE_H = BN * STH;        // 4608 halves per tile
constexpr int SMEM_BYTES = 4 * TILE_H * 2;   // 36864 B
constexpr float NEG = 1e10f;

__device__ __half g_qh[NEL];
__device__ __half g_kh[NEL];
__device__ __half g_vh[NEL];

__global__ __launch_bounds__(256)
void f2h_kernel(const float* __restrict__ src, int which) {
    __half* dst = (which == 0) ? g_qh : (which == 1) ? g_kh : g_vh;
    const int i = (blockIdx.x * 256 + threadIdx.x) * 8;
    if (i >= NEL) return;
    const float4 a = *reinterpret_cast<const float4*>(src + i);
    const float4 b = *reinterpret_cast<const float4*>(src + i + 4);
    __half2 h0 = __float22half2_rn(make_float2(a.x, a.y));
    __half2 h1 = __float22half2_rn(make_float2(a.z, a.w));
    __half2 h2 = __float22half2_rn(make_float2(b.x, b.y));
    __half2 h3 = __float22half2_rn(make_float2(b.z, b.w));
    uint4 o;
    o.x = *reinterpret_cast<unsigned*>(&h0);
    o.y = *reinterpret_cast<unsigned*>(&h1);
    o.z = *reinterpret_cast<unsigned*>(&h2);
    o.w = *reinterpret_cast<unsigned*>(&h3);
    *reinterpret_cast<uint4*>(reinterpret_cast<char*>(dst) + (size_t)i * 2) = o;
}

__device__ __forceinline__ void hmma(float c[4],
                                     unsigned a0, unsigned a1, unsigned a2, unsigned a3,
                                     unsigned b0, unsigned b1) {
    asm("mma.sync.aligned.m16n8k16.row.col.f32.f16.f16.f32 "
        "{%0,%1,%2,%3},{%4,%5,%6,%7},{%8,%9},{%0,%1,%2,%3};"
        : "+f"(c[0]), "+f"(c[1]), "+f"(c[2]), "+f"(c[3])
        : "r"(a0), "r"(a1), "r"(a2), "r"(a3), "r"(b0), "r"(b1));
}

__device__ __forceinline__ void ldsm4(unsigned& a, unsigned& b, unsigned& c, unsigned& d,
                                      unsigned addr) {
    asm volatile("ldmatrix.sync.aligned.m8n8.x4.shared.b16 {%0,%1,%2,%3}, [%4];"
                 : "=r"(a), "=r"(b), "=r"(c), "=r"(d) : "r"(addr));
}

__device__ __forceinline__ void ldsm4t(unsigned& a, unsigned& b, unsigned& c, unsigned& d,
                                       unsigned addr) {
    asm volatile("ldmatrix.sync.aligned.m8n8.x4.trans.shared.b16 {%0,%1,%2,%3}, [%4];"
                 : "=r"(a), "=r"(b), "=r"(c), "=r"(d) : "r"(addr));
}

__device__ __forceinline__ void cp16(__half* dst_smem, const __half* src) {
    unsigned d = (unsigned)__cvta_generic_to_shared(dst_smem);
    asm volatile("cp.async.cg.shared.global [%0], [%1], 16;" :: "r"(d), "l"(src));
}

__device__ __forceinline__ unsigned packh2(float lo, float hi) {
    __half2 h = __float22half2_rn(make_float2(lo, hi));
    return *reinterpret_cast<unsigned*>(&h);
}

__global__ __launch_bounds__(128, 4)
void attn_fp16_kernel(const int* __restrict__ M, float* __restrict__ O)
{
    extern __shared__ __half sm[];
    __half* Kb0 = sm;
    __half* Kb1 = sm + TILE_H;
    __half* Vb0 = sm + 2 * TILE_H;
    __half* Vb1 = sm + 3 * TILE_H;

    const int tid  = threadIdx.x;
    const int lane = tid & 31;
    const int warp = tid >> 5;
    const int r0 = lane >> 2;
    const int jj = lane & 3;

    const int b  = blockIdx.y;
    const int q0 = blockIdx.x * BM;
    const int m0 = warp * 16;

    const __half* qh = g_qh + ((long)b * TO + q0) * DD;
    const __half* kh = g_kh + (long)b * TI * DD;
    const __half* vh = g_vh + (long)b * TI * DD;
    const int* mbA = M + ((long)((long)b * TO + q0 + m0 + r0)) * TI;
    const int* mbB = mbA + 8L * TI;

    // staging: 128 threads cover 16 rows x 64 halves per pass, 4 passes/tile
    const int sr = tid >> 3;          // 0..15
    const int sc = (tid & 7) << 3;    // 0..56 (halves)

    // ldmatrix lane offsets (halves -> bytes)
    const unsigned kfoff = ((((lane & 7) + (((lane >> 4) & 1) << 3)) * STH) +
                            (((lane >> 3) & 1) << 3)) * 2u;
    const unsigned vfoff = ((((lane & 7) + (((lane >> 3) & 1) << 3)) * STH) +
                            (((lane >> 4) & 1) << 3)) * 2u;
    const unsigned qfoff = (((m0 + (lane & 7) + (((lane >> 3) & 1) << 3)) * STH) +
                            (((lane >> 4) & 1) << 3)) * 2u;

    const unsigned kbu0 = (unsigned)__cvta_generic_to_shared(Kb0);
    const unsigned kbu1 = (unsigned)__cvta_generic_to_shared(Kb1);
    const unsigned vbu0 = (unsigned)__cvta_generic_to_shared(Vb0);
    const unsigned vbu1 = (unsigned)__cvta_generic_to_shared(Vb1);

    // ---- group A: Q tile -> Vb1 staging
    #pragma unroll
    for (int i = 0; i < 4; ++i) {
        const int r = sr + i * 16;
        cp16(Vb1 + r * STH + sc, qh + (long)r * DD + sc);
    }
    asm volatile("cp.async.commit_group;");

    // ---- group B: tile 0 K/V
    #pragma unroll
    for (int i = 0; i < 4; ++i) {
        const int r = sr + i * 16;
        cp16(Kb0 + r * STH + sc, kh + (long)r * DD + sc);
        cp16(Vb0 + r * STH + sc, vh + (long)r * DD + sc);
    }
    asm volatile("cp.async.commit_group;");

    asm volatile("cp.async.wait_group 1;");   // Q resident
    __syncthreads();

    unsigned qa[4][4];
    #pragma unroll
    for (int c = 0; c < 4; ++c)
        ldsm4(qa[c][0], qa[c][1], qa[c][2], qa[c][3],
              vbu1 + qfoff + (unsigned)(c * 16 * 2));
    __syncthreads();   // Vb1 free

    // ---- group C: tile 1 K/V
    #pragma unroll
    for (int i = 0; i < 4; ++i) {
        const int r = sr + i * 16;
        cp16(Kb1 + r * STH + sc, kh + (long)(BN + r) * DD + sc);
        cp16(Vb1 + r * STH + sc, vh + (long)(BN + r) * DD + sc);
    }
    asm volatile("cp.async.commit_group;");

    float acc[8][4];
    #pragma unroll
    for (int dt = 0; dt < 8; ++dt)
        #pragma unroll
        for (int r = 0; r < 4; ++r) acc[dt][r] = 0.0f;

    float mA = -1e30f, mB = -1e30f, lA = 0.0f, lB = 0.0f;

    for (int t = 0; t < TI / BN; ++t) {
        asm volatile("cp.async.wait_group 1;");
        __syncthreads();   // tile t resident

        const unsigned kbu = (t & 1) ? kbu1 : kbu0;
        const unsigned vbu = (t & 1) ? vbu1 : vbu0;

        // ---- GEMM1: S = Q K^T
        float s[8][4];
        #pragma unroll
        for (int nt = 0; nt < 8; ++nt)
            #pragma unroll
            for (int r = 0; r < 4; ++r) s[nt][r] = 0.0f;

        #pragma unroll
        for (int c = 0; c < 4; ++c) {
            #pragma unroll
            for (int p = 0; p < 4; ++p) {
                unsigned w0, w1, w2, w3;
                ldsm4(w0, w1, w2, w3,
                      kbu + kfoff + (unsigned)(((p * 16 * STH) + c * 16) * 2));
                hmma(s[2 * p],     qa[c][0], qa[c][1], qa[c][2], qa[c][3], w0, w1);
                hmma(s[2 * p + 1], qa[c][0], qa[c][1], qa[c][2], qa[c][3], w2, w3);
            }
        }

        // ---- mask + scale
        const int tbase = t * BN;
        #pragma unroll
        for (int nt = 0; nt < 8; ++nt) {
            const int col = tbase + 8 * nt + 2 * jj;
            const int2 ma  = *reinterpret_cast<const int2*>(mbA + col);
            const int2 mb2 = *reinterpret_cast<const int2*>(mbB + col);
            s[nt][0] = ma.x  ? s[nt][0] * 0.125f : -NEG;
            s[nt][1] = ma.y  ? s[nt][1] * 0.125f : -NEG;
            s[nt][2] = mb2.x ? s[nt][2] * 0.125f : -NEG;
            s[nt][3] = mb2.y ? s[nt][3] * 0.125f : -NEG;
        }

        // ---- online softmax (fp32)
        float tmA = -1e30f, tmB = -1e30f;
        #pragma unroll
        for (int nt = 0; nt < 8; ++nt) {
            tmA = fmaxf(tmA, fmaxf(s[nt][0], s[nt][1]));
            tmB = fmaxf(tmB, fmaxf(s[nt][2], s[nt][3]));
        }
        tmA = fmaxf(tmA, __shfl_xor_sync(0xffffffffu, tmA, 1));
        tmA = fmaxf(tmA, __shfl_xor_sync(0xffffffffu, tmA, 2));
        tmB = fmaxf(tmB, __shfl_xor_sync(0xffffffffu, tmB, 1));
        tmB = fmaxf(tmB, __shfl_xor_sync(0xffffffffu, tmB, 2));

        const float mnA = fmaxf(mA, tmA);
        const float mnB = fmaxf(mB, tmB);
        const float sfA = __expf(mA - mnA);
        const float sfB = __expf(mB - mnB);
        mA = mnA; mB = mnB;

        float psA = 0.0f, psB = 0.0f;
        #pragma unroll
        for (int nt = 0; nt < 8; ++nt) {
            s[nt][0] = __expf(s[nt][0] - mnA);
            s[nt][1] = __expf(s[nt][1] - mnA);
            s[nt][2] = __expf(s[nt][2] - mnB);
            s[nt][3] = __expf(s[nt][3] - mnB);
            psA += s[nt][0] + s[nt][1];
            psB += s[nt][2] + s[nt][3];
        }
        psA += __shfl_xor_sync(0xffffffffu, psA, 1);
        psA += __shfl_xor_sync(0xffffffffu, psA, 2);
        psB += __shfl_xor_sync(0xffffffffu, psB, 1);
        psB += __shfl_xor_sync(0xffffffffu, psB, 2);
        lA = lA * sfA + psA;
        lB = lB * sfB + psB;

        #pragma unroll
        for (int dt = 0; dt < 8; ++dt) {
            acc[dt][0] *= sfA; acc[dt][1] *= sfA;
            acc[dt][2] *= sfB; acc[dt][3] *= sfB;
        }

        // ---- GEMM2: acc += P V  (C-frag is already A-frag layout: just pack)
        #pragma unroll
        for (int c = 0; c < 4; ++c) {
            const unsigned a0 = packh2(s[2 * c][0],     s[2 * c][1]);
            const unsigned a1 = packh2(s[2 * c][2],     s[2 * c][3]);
            const unsigned a2 = packh2(s[2 * c + 1][0], s[2 * c + 1][1]);
            const unsigned a3 = packh2(s[2 * c + 1][2], s[2 * c + 1][3]);
            #pragma unroll
            for (int p = 0; p < 4; ++p) {
                unsigned v0, v1, v2, v3;
                ldsm4t(v0, v1, v2, v3,
                       vbu + vfoff + (unsigned)(((c * 16 * STH) + p * 16) * 2));
                hmma(acc[2 * p],     a0, a1, a2, a3, v0, v1);
                hmma(acc[2 * p + 1], a0, a1, a2, a3, v2, v3);
            }
        }

        __syncthreads();   // done with buffer t&1

        // ---- prefetch tile t+2 into buffer t&1
        if (t + 2 < TI / BN) {
            __half* Kn = (t & 1) ? Kb1 : Kb0;
            __half* Vn = (t & 1) ? Vb1 : Vb0;
            const long off = (long)(t + 2) * BN;
            #pragma unroll
            for (int i = 0; i < 4; ++i) {
                const int r = sr + i * 16;
                cp16(Kn + r * STH + sc, kh + (off + r) * DD + sc);
                cp16(Vn + r * STH + sc, vh + (off + r) * DD + sc);
            }
        }
        asm volatile("cp.async.commit_group;");
    }

    // ---- epilogue: normalize, store
    const float invA = 1.0f / lA;
    const float invB = 1.0f / lB;
    float* oA = O + ((long)b * TO + q0 + m0 + r0) * DD;
    float* oB = oA + 8L * DD;
    #pragma unroll
    for (int dt = 0; dt < 8; ++dt) {
        const int c = 8 * dt + 2 * jj;
        float2 ra, rb;
        ra.x = acc[dt][0] * invA; ra.y = acc[dt][1] * invA;
        rb.x = acc[dt][2] * invB; rb.y = acc[dt][3] * invB;
        *reinterpret_cast<float2*>(oA + c) = ra;
        *reinterpret_cast<float2*>(oB + c) = rb;
    }
}

}  // namespace

extern "C" void kernel_launch(void* const* d_in, const int* in_sizes, int n_in,
                              void* d_out, int out_size)
{
    const float* q = (const float*)d_in[0];
    const float* k = (const float*)d_in[1];
    const float* v = (const float*)d_in[2];
    const int*   m = (const int*)d_in[3];
    float* out = (float*)d_out;

    // pre-pass: fp32 -> fp16 (NEL/8 threads each)
    const int cvt_blocks = NEL / (256 * 8);
    f2h_kernel<<<cvt_blocks, 256>>>(q, 0);
    f2h_kernel<<<cvt_blocks, 256>>>(k, 1);
    f2h_kernel<<<cvt_blocks, 256>>>(v, 2);

    dim3 grid(TO / BM, 16);
    dim3 block(128);
    attn_fp16_kernel<<<grid, block, SMEM_BYTES>>>(m, out);
}